// round 9
// baseline (speedup 1.0000x reference)
#include <cuda_runtime.h>
#include <cuda_fp16.h>

#define B_  256
#define C_  1152
#define N_  10
#define ND_ 160          // N_*D_
#define CCH_ 144         // k1 c-chunks of 8
#define QCH_ 8           // routing c-chunks of 144

// u_hat scratch (fp16), per (b,c) p-layout: [g(0..1)][n(0..9)][8]; d = g*8+dd
__device__ unsigned short g_uhat[(size_t)256*1152*160];
// per-c-chunk partial sums of u_hat over c (plain [n*16+d]): [cchunk(144)][b][160]
__device__ float g_s0p[(size_t)CCH_*256*160];
// routing per-chunk partial s: [qchunk(8)][b][160] plain layout (two buffers)
__device__ float g_sp [(size_t)QCH_*256*160];
__device__ float g_sp2[(size_t)QCH_*256*160];
// v1 per b, plain layout
__device__ float g_v[(size_t)256*160];

// ---------------------------------------------------------------------------
// K1: u_hat[b,n,c,d] = sum_i W[n,c,d,i]*x[b,c,i]
// grid (144 c-chunks of 8, 4 b-chunks of 64), 320 threads:
// warp = n, lane>>3 = q (d-quarter), lane&7 = c_local. W in regs, x staged in smem.
// ---------------------------------------------------------------------------
__global__ __launch_bounds__(320, 3) void k1_gemm(const float* __restrict__ x,
                                                  const float* __restrict__ W)
{
    __shared__ float xs[64*64];       // x[b_local][c_local*8+i], 16 KB

    const int t    = threadIdx.x;
    const int n    = t >> 5;          // warp id = output capsule
    const int lane = t & 31;
    const int q    = lane >> 3;       // d-quarter 0..3
    const int cl   = lane & 7;        // c within block
    const int c    = blockIdx.x * 8 + cl;
    const int b0   = blockIdx.y * 64;

    // W regs: Wr[dd*8+i] = W[n][c][q*4+dd][i]
    float Wr[32];
    {
        const float4* Wp = reinterpret_cast<const float4*>(
            W + ((size_t)(n*C_ + c))*128 + q*32);
#pragma unroll
        for (int k = 0; k < 8; ++k) {
            float4 f = Wp[k];
            Wr[4*k]=f.x; Wr[4*k+1]=f.y; Wr[4*k+2]=f.z; Wr[4*k+3]=f.w;
        }
    }

    // cooperative x stage: 64 b's x 64 floats (8 c x 8 i), contiguous per b
    for (int idx = t; idx < 1024; idx += 320) {
        int bl = idx >> 4;            // 16 float4 per b
        int r  = idx & 15;
        reinterpret_cast<float4*>(xs)[bl*16 + r] =
            reinterpret_cast<const float4*>(
                x + (size_t)(b0 + bl)*(C_*8) + blockIdx.x*64)[r];
    }
    __syncthreads();

    // p-layout inner offset for this thread's 4 d's (d = q*4..q*4+3)
    const size_t ubase = (size_t)c*160 + (size_t)(q>>1)*80 + n*8 + (q&1)*4;
    const size_t sbase = (size_t)blockIdx.x*(B_*ND_) + n*16 + q*4;   // plain layout

#pragma unroll 2
    for (int bl = 0; bl < 64; ++bl) {
        const int b = b0 + bl;
        const float4* xr = reinterpret_cast<const float4*>(xs + bl*64 + cl*8);
        float4 f0 = xr[0], f1 = xr[1];
        float xv[8];
        xv[0]=f0.x; xv[1]=f0.y; xv[2]=f0.z; xv[3]=f0.w;
        xv[4]=f1.x; xv[5]=f1.y; xv[6]=f1.z; xv[7]=f1.w;

        float u[4];
#pragma unroll
        for (int dd = 0; dd < 4; ++dd) {
            float a = 0.f;
#pragma unroll
            for (int i = 0; i < 8; ++i) a = fmaf(Wr[dd*8+i], xv[i], a);
            u[dd] = a;
        }

        // store fp16 (8 bytes)
        __half2 h01 = __floats2half2_rn(u[0], u[1]);
        __half2 h23 = __floats2half2_rn(u[2], u[3]);
        uint2 val;
        val.x = *reinterpret_cast<unsigned int*>(&h01);
        val.y = *reinterpret_cast<unsigned int*>(&h23);
        *reinterpret_cast<uint2*>(g_uhat + (size_t)b*(C_*160) + ubase) = val;

        // per-chunk s0 partial: reduce over the 8 c lanes
        float p0=u[0], p1=u[1], p2=u[2], p3=u[3];
#pragma unroll
        for (int off = 1; off < 8; off <<= 1) {
            p0 += __shfl_xor_sync(0xffffffffu, p0, off);
            p1 += __shfl_xor_sync(0xffffffffu, p1, off);
            p2 += __shfl_xor_sync(0xffffffffu, p2, off);
            p3 += __shfl_xor_sync(0xffffffffu, p3, off);
        }
        if (cl == 0)
            *reinterpret_cast<float4*>(g_s0p + sbase + (size_t)b*ND_) =
                make_float4(p0, p1, p2, p3);
    }
}

// ---------------------------------------------------------------------------
// K_red_s0: v1 = squash(0.1 * sum of 144 s0 partials). grid 256, 160 threads.
// ---------------------------------------------------------------------------
__global__ __launch_bounds__(160) void k_red_s0()
{
    const int b = blockIdx.x;
    const int t = threadIdx.x;

    float s = 0.f;
#pragma unroll 4
    for (int k = 0; k < CCH_; ++k)
        s += g_s0p[((size_t)k*B_ + b)*ND_ + t];
    s *= 0.1f;

    float sq = s*s;
#pragma unroll
    for (int o = 1; o < 16; o <<= 1)
        sq += __shfl_xor_sync(0xffffffffu, sq, o);   // sum over 16 d's
    float f = sq / (1.f + sq) / (sqrtf(sq) + 1e-8f);
    g_v[(size_t)b*ND_ + t] = s * f;
}

// ---------------------------------------------------------------------------
// K_red_out: v = squash(sum of 8 pass-2 partials) -> out. grid 256, 160 thr.
// ---------------------------------------------------------------------------
__global__ __launch_bounds__(160) void k_red_out(float* __restrict__ out)
{
    const int b = blockIdx.x;
    const int t = threadIdx.x;

    float s = 0.f;
#pragma unroll
    for (int k = 0; k < QCH_; ++k)
        s += g_sp2[((size_t)k*B_ + b)*ND_ + t];

    float sq = s*s;
#pragma unroll
    for (int o = 1; o < 16; o <<= 1)
        sq += __shfl_xor_sync(0xffffffffu, sq, o);
    float f = sq / (1.f + sq) / (sqrtf(sq) + 1e-8f);
    out[(size_t)b*ND_ + t] = s * f;
}

// ---------------------------------------------------------------------------
// K2 pass: one routing iteration over a 144-c chunk. NO logit storage:
//   PASS 1: logit = u.v1            (vcur = v1)
//   PASS 2: logit = u.(v1+v2)       (vcur computed in prologue from g_sp)
// grid (8 qchunks, 256 b), 256 threads = 8 warps.
// lane = g*16+n: g = c-parity (warp covers 2 c/step), n = capsule; 9 steps.
// ---------------------------------------------------------------------------
__device__ __forceinline__ void cvt8(const uint4& H, float* u)
{
    unsigned int r[4] = {H.x, H.y, H.z, H.w};
#pragma unroll
    for (int k = 0; k < 4; ++k) {
        __half2 h = *reinterpret_cast<__half2*>(&r[k]);
        float2 f = __half22float2(h);
        u[2*k] = f.x; u[2*k+1] = f.y;
    }
}

template<int PASS>
__global__ __launch_bounds__(256, 3) void k2_pass()
{
    __shared__ float sred[8*ND_];
    __shared__ float vsm[ND_];

    const int  qc = blockIdx.x;       // c-chunk 0..7
    const int  b  = blockIdx.y;
    const int  t  = threadIdx.x;
    const int  w  = t >> 5;
    const int  l  = t & 31;
    const int  g  = l >> 4;
    const int  n  = l & 15;
    const bool act = (n < N_);

    // prologue: vcur into vsm
    if (t < ND_) {
        if (PASS == 1) {
            vsm[t] = g_v[(size_t)b*ND_ + t];
        } else {
            float s = 0.f;
#pragma unroll
            for (int k = 0; k < QCH_; ++k)
                s += g_sp[((size_t)k*B_ + b)*ND_ + t];
            float sq = s*s;
#pragma unroll
            for (int o = 1; o < 16; o <<= 1)
                sq += __shfl_xor_sync(0xffffffffu, sq, o);
            float f = sq / (1.f + sq) / (sqrtf(sq) + 1e-8f);
            vsm[t] = s * f + g_v[(size_t)b*ND_ + t];    // v1 + v2
        }
    }
    __syncthreads();

    float vreg[16];
#pragma unroll
    for (int d = 0; d < 16; ++d) vreg[d] = act ? vsm[n*16 + d] : 0.f;

    float sacc[16];
#pragma unroll
    for (int d = 0; d < 16; ++d) sacc[d] = 0.f;

    const unsigned short* uh = g_uhat + (size_t)b*(C_*160);
    int c = qc*144 + 2*w + g;

    uint4 A0, A1;
    if (act) {
        const unsigned short* p = uh + (size_t)c*160 + n*8;
        A0 = *reinterpret_cast<const uint4*>(p);
        A1 = *reinterpret_cast<const uint4*>(p + 80);
    }

#pragma unroll
    for (int i = 0; i < 9; ++i) {
        uint4 a0 = A0, a1 = A1;
        if (act && i < 8) {
            const unsigned short* p = uh + (size_t)(c+16)*160 + n*8;
            A0 = *reinterpret_cast<const uint4*>(p);
            A1 = *reinterpret_cast<const uint4*>(p + 80);
        }

        float u[16];
        cvt8(a0, u);
        cvt8(a1, u + 8);

        float uv0 = 0.f, uv1 = 0.f;
#pragma unroll
        for (int d = 0; d < 16; d += 2) {
            uv0 = fmaf(u[d],   vreg[d],   uv0);
            uv1 = fmaf(u[d+1], vreg[d+1], uv1);
        }
        float logit = uv0 + uv1;

        float e = act ? __expf(logit) : 0.f;
        float ssum = e;
#pragma unroll
        for (int o = 8; o; o >>= 1)
            ssum += __shfl_xor_sync(0xffffffffu, ssum, o);
        float coef = e * __fdividef(1.f, ssum);

#pragma unroll
        for (int d = 0; d < 16; ++d) sacc[d] = fmaf(coef, u[d], sacc[d]);

        c += 16;
    }

    // combine the two c-parity halves of each warp
#pragma unroll
    for (int d = 0; d < 16; ++d)
        sacc[d] += __shfl_xor_sync(0xffffffffu, sacc[d], 16);

    if (g == 0 && act) {
#pragma unroll
        for (int d = 0; d < 16; ++d) sred[w*ND_ + n*16 + d] = sacc[d];
    }
    __syncthreads();
    if (t < ND_) {
        float a = 0.f;
#pragma unroll
        for (int k = 0; k < 8; ++k) a += sred[k*ND_ + t];
        float* dst = (PASS == 1) ? g_sp : g_sp2;
        dst[((size_t)qc*B_ + b)*ND_ + t] = a;
    }
}

// ---------------------------------------------------------------------------
extern "C" void kernel_launch(void* const* d_in, const int* in_sizes, int n_in,
                              void* d_out, int out_size)
{
    const float* x;
    const float* W;
    if (in_sizes[0] == B_*C_*8) { x = (const float*)d_in[0]; W = (const float*)d_in[1]; }
    else                        { x = (const float*)d_in[1]; W = (const float*)d_in[0]; }
    float* out = (float*)d_out;

    k1_gemm<<<dim3(CCH_, 4), 320>>>(x, W);
    k_red_s0<<<B_, 160>>>();                       // s0 partials -> v1
    k2_pass<1><<<dim3(QCH_, B_), 256>>>();         // logit=u.v1 -> partial s (g_sp)
    k2_pass<2><<<dim3(QCH_, B_), 256>>>();         // v2 in prologue; logit=u.(v1+v2) -> g_sp2
    k_red_out<<<B_, 160>>>(out);                   // -> v3 = output
}

// round 11
// speedup vs baseline: 1.0852x; 1.0852x over previous
#include <cuda_runtime.h>
#include <cuda_fp16.h>

#define B_  256
#define C_  1152
#define N_  10
#define ND_ 160          // N_*D_
#define CCH_ 144         // k1 c-chunks of 8
#define QCH_ 4           // routing c-chunks of 288

// u_hat scratch (fp16), per (b,c) p-layout: [g(0..1)][n(0..9)][8]; d = g*8+dd
__device__ unsigned short g_uhat[(size_t)256*1152*160];
// per-c-chunk partial sums of u_hat over c (plain [n*16+d]): [cchunk(144)][b][160]
__device__ float g_s0p[(size_t)CCH_*256*160];
// routing per-chunk partial s: [qchunk(4)][b][160] plain layout (two buffers)
__device__ float g_sp [(size_t)QCH_*256*160];
__device__ float g_sp2[(size_t)QCH_*256*160];
// v1 per b, plain layout
__device__ float g_v[(size_t)256*160];

// ---------------------------------------------------------------------------
// K1: u_hat[b,n,c,d] = sum_i W[n,c,d,i]*x[b,c,i]
// grid (144 c-chunks of 8, 4 b-chunks of 64), 320 threads:
// warp = n, lane>>3 = q (d-quarter), lane&7 = c_local. W in regs, x in smem.
// u_hat staged through smem in 8-b batches -> fully coalesced STG.128 sweeps.
// ---------------------------------------------------------------------------
__global__ __launch_bounds__(320, 3) void k1_gemm(const float* __restrict__ x,
                                                  const float* __restrict__ W)
{
    __shared__ float xs[64*64];                         // 16 KB
    __shared__ alignas(16) unsigned short usm[8*8*168]; // 21 KB: [bl][cl][168 pad]

    const int t    = threadIdx.x;
    const int n    = t >> 5;          // warp id = output capsule
    const int lane = t & 31;
    const int q    = lane >> 3;       // d-quarter 0..3
    const int cl   = lane & 7;        // c within block
    const int c    = blockIdx.x * 8 + cl;
    const int b0   = blockIdx.y * 64;

    // W regs: Wr[dd*8+i] = W[n][c][q*4+dd][i]
    float Wr[32];
    {
        const float4* Wp = reinterpret_cast<const float4*>(
            W + ((size_t)(n*C_ + c))*128 + q*32);
#pragma unroll
        for (int k = 0; k < 8; ++k) {
            float4 f = Wp[k];
            Wr[4*k]=f.x; Wr[4*k+1]=f.y; Wr[4*k+2]=f.z; Wr[4*k+3]=f.w;
        }
    }

    // cooperative x stage: 64 b's x 64 floats (8 c x 8 i), contiguous per b
    for (int idx = t; idx < 1024; idx += 320) {
        int bl = idx >> 4;            // 16 float4 per b
        int r  = idx & 15;
        reinterpret_cast<float4*>(xs)[bl*16 + r] =
            reinterpret_cast<const float4*>(
                x + (size_t)(b0 + bl)*(C_*8) + blockIdx.x*64)[r];
    }
    __syncthreads();

    // p-layout inner offset for this thread's 4 d's (d = q*4..q*4+3)
    const int poff = (q>>1)*80 + n*8 + (q&1)*4;
    const size_t sbase = (size_t)blockIdx.x*(B_*ND_) + n*16 + q*4;   // plain layout

    for (int bg = 0; bg < 8; ++bg) {
        const int b_base = b0 + bg*8;

#pragma unroll
        for (int bl = 0; bl < 8; ++bl) {
            const int b = b_base + bl;
            const float4* xr = reinterpret_cast<const float4*>(xs + (b - b0)*64 + cl*8);
            float4 f0 = xr[0], f1 = xr[1];
            float xv[8];
            xv[0]=f0.x; xv[1]=f0.y; xv[2]=f0.z; xv[3]=f0.w;
            xv[4]=f1.x; xv[5]=f1.y; xv[6]=f1.z; xv[7]=f1.w;

            float u[4];
#pragma unroll
            for (int dd = 0; dd < 4; ++dd) {
                float a = 0.f;
#pragma unroll
                for (int i = 0; i < 8; ++i) a = fmaf(Wr[dd*8+i], xv[i], a);
                u[dd] = a;
            }

            // pack fp16, stage into smem (coalesced sweep later)
            __half2 h01 = __floats2half2_rn(u[0], u[1]);
            __half2 h23 = __floats2half2_rn(u[2], u[3]);
            uint2 val;
            val.x = *reinterpret_cast<unsigned int*>(&h01);
            val.y = *reinterpret_cast<unsigned int*>(&h23);
            *reinterpret_cast<uint2*>(usm + (bl*8 + cl)*168 + poff) = val;

            // per-chunk s0 partial: reduce over the 8 c lanes
            float p0=u[0], p1=u[1], p2=u[2], p3=u[3];
#pragma unroll
            for (int off = 1; off < 8; off <<= 1) {
                p0 += __shfl_xor_sync(0xffffffffu, p0, off);
                p1 += __shfl_xor_sync(0xffffffffu, p1, off);
                p2 += __shfl_xor_sync(0xffffffffu, p2, off);
                p3 += __shfl_xor_sync(0xffffffffu, p3, off);
            }
            if (cl == 0)
                *reinterpret_cast<float4*>(g_s0p + sbase + (size_t)b*ND_) =
                    make_float4(p0, p1, p2, p3);
        }
        __syncthreads();

        // coalesced sweep: 8 b x 8 c x 160 halfs = 1280 uint4
#pragma unroll
        for (int it = 0; it < 4; ++it) {
            int j   = it*320 + t;          // 0..1279
            int bl2 = j / 160;
            int r   = j - bl2*160;
            int cL  = r / 20;
            int h   = r - cL*20;           // uint4 index within c (8 halfs each)
            uint4 v = *reinterpret_cast<const uint4*>(usm + (bl2*8 + cL)*168 + h*8);
            *reinterpret_cast<uint4*>(
                g_uhat + (size_t)(b_base + bl2)*(C_*160)
                       + (size_t)(blockIdx.x*8 + cL)*160 + h*8) = v;
        }
        __syncthreads();
    }
}

// ---------------------------------------------------------------------------
// K_red_s0: v1 = squash(0.1 * sum of 144 s0 partials). grid 256, 160 threads.
// ---------------------------------------------------------------------------
__global__ __launch_bounds__(160) void k_red_s0()
{
    const int b = blockIdx.x;
    const int t = threadIdx.x;

    float s = 0.f;
#pragma unroll 4
    for (int k = 0; k < CCH_; ++k)
        s += g_s0p[((size_t)k*B_ + b)*ND_ + t];
    s *= 0.1f;

    float sq = s*s;
#pragma unroll
    for (int o = 1; o < 16; o <<= 1)
        sq += __shfl_xor_sync(0xffffffffu, sq, o);   // sum over 16 d's
    float f = sq / (1.f + sq) / (sqrtf(sq) + 1e-8f);
    g_v[(size_t)b*ND_ + t] = s * f;
}

// ---------------------------------------------------------------------------
// K_red_out: v = squash(sum of 4 pass-2 partials) -> out. grid 256, 160 thr.
// ---------------------------------------------------------------------------
__global__ __launch_bounds__(160) void k_red_out(float* __restrict__ out)
{
    const int b = blockIdx.x;
    const int t = threadIdx.x;

    float s = 0.f;
#pragma unroll
    for (int k = 0; k < QCH_; ++k)
        s += g_sp2[((size_t)k*B_ + b)*ND_ + t];

    float sq = s*s;
#pragma unroll
    for (int o = 1; o < 16; o <<= 1)
        sq += __shfl_xor_sync(0xffffffffu, sq, o);
    float f = sq / (1.f + sq) / (sqrtf(sq) + 1e-8f);
    out[(size_t)b*ND_ + t] = s * f;
}

// ---------------------------------------------------------------------------
// K2 pass: one routing iteration over a 288-c chunk. No logit storage:
//   PASS 1: vcur = v1.   PASS 2: vcur = v1 + v2 (computed in prologue).
//   logit = u . vcur in both passes.
// grid (4 qchunks, 256 b), 256 threads = 8 warps.
// lane = g*16+n: g = c-parity, n = capsule. Two independent chains per iter.
// ---------------------------------------------------------------------------
__device__ __forceinline__ void cvt8(const uint4& H, float* u)
{
    unsigned int r[4] = {H.x, H.y, H.z, H.w};
#pragma unroll
    for (int k = 0; k < 4; ++k) {
        __half2 h = *reinterpret_cast<__half2*>(&r[k]);
        float2 f = __half22float2(h);
        u[2*k] = f.x; u[2*k+1] = f.y;
    }
}

__device__ __forceinline__ void route_step(
    uint4 X0, uint4 X1, bool act,
    const float* __restrict__ vreg, float* __restrict__ sacc)
{
    float u[16];
    cvt8(X0, u);
    cvt8(X1, u + 8);

    float uv0 = 0.f, uv1 = 0.f;
#pragma unroll
    for (int d = 0; d < 16; d += 2) {
        uv0 = fmaf(u[d],   vreg[d],   uv0);
        uv1 = fmaf(u[d+1], vreg[d+1], uv1);
    }
    float logit = uv0 + uv1;

    float e = act ? __expf(logit) : 0.f;
    float ssum = e;
#pragma unroll
    for (int o = 8; o; o >>= 1)
        ssum += __shfl_xor_sync(0xffffffffu, ssum, o);
    float coef = e * __fdividef(1.f, ssum);

#pragma unroll
    for (int d = 0; d < 16; ++d) sacc[d] = fmaf(coef, u[d], sacc[d]);
}

template<int PASS>
__global__ __launch_bounds__(256, 3) void k2_pass()
{
    __shared__ float sred[8*ND_];
    __shared__ float vsm[ND_];

    const int  qc = blockIdx.x;       // c-chunk 0..3 (288 c each)
    const int  b  = blockIdx.y;
    const int  t  = threadIdx.x;
    const int  w  = t >> 5;
    const int  l  = t & 31;
    const int  g  = l >> 4;
    const int  n  = l & 15;
    const bool act = (n < N_);

    // prologue: vcur into vsm
    if (t < ND_) {
        if (PASS == 1) {
            vsm[t] = g_v[(size_t)b*ND_ + t];
        } else {
            float s = 0.f;
#pragma unroll
            for (int k = 0; k < QCH_; ++k)
                s += g_sp[((size_t)k*B_ + b)*ND_ + t];
            float sq = s*s;
#pragma unroll
            for (int o = 1; o < 16; o <<= 1)
                sq += __shfl_xor_sync(0xffffffffu, sq, o);
            float f = sq / (1.f + sq) / (sqrtf(sq) + 1e-8f);
            vsm[t] = s * f + g_v[(size_t)b*ND_ + t];    // v1 + v2
        }
    }
    __syncthreads();

    float vreg[16];
#pragma unroll
    for (int d = 0; d < 16; ++d) vreg[d] = act ? vsm[n*16 + d] : 0.f;

    float sacc[16];
#pragma unroll
    for (int d = 0; d < 16; ++d) sacc[d] = 0.f;

    const unsigned short* uh = g_uhat + (size_t)b*(C_*160);
    int c = qc*288 + 2*w + g;

    uint4 A0, A1, B0, B1;
    if (act) {
        const unsigned short* p = uh + (size_t)c*160 + n*8;
        A0 = *reinterpret_cast<const uint4*>(p);
        A1 = *reinterpret_cast<const uint4*>(p + 80);
        const unsigned short* pb = p + 16*160;
        B0 = *reinterpret_cast<const uint4*>(pb);
        B1 = *reinterpret_cast<const uint4*>(pb + 80);
    }

    for (int i = 0; i < 18; i += 2) {
        uint4 a0 = A0, a1 = A1;
        if (i + 2 < 18 && act) {
            const unsigned short* p = uh + (size_t)(c+32)*160 + n*8;
            A0 = *reinterpret_cast<const uint4*>(p);
            A1 = *reinterpret_cast<const uint4*>(p + 80);
        }
        route_step(a0, a1, act, vreg, sacc);

        uint4 b0 = B0, b1 = B1;
        if (i + 3 < 18 && act) {
            const unsigned short* p = uh + (size_t)(c+48)*160 + n*8;
            B0 = *reinterpret_cast<const uint4*>(p);
            B1 = *reinterpret_cast<const uint4*>(p + 80);
        }
        route_step(b0, b1, act, vreg, sacc);

        c += 32;
    }

    // combine the two c-parity halves of each warp
#pragma unroll
    for (int d = 0; d < 16; ++d)
        sacc[d] += __shfl_xor_sync(0xffffffffu, sacc[d], 16);

    if (g == 0 && act) {
#pragma unroll
        for (int d = 0; d < 16; ++d) sred[w*ND_ + n*16 + d] = sacc[d];
    }
    __syncthreads();
    if (t < ND_) {
        float a = 0.f;
#pragma unroll
        for (int k = 0; k < 8; ++k) a += sred[k*ND_ + t];
        float* dst = (PASS == 1) ? g_sp : g_sp2;
        dst[((size_t)qc*B_ + b)*ND_ + t] = a;
    }
}

// ---------------------------------------------------------------------------
extern "C" void kernel_launch(void* const* d_in, const int* in_sizes, int n_in,
                              void* d_out, int out_size)
{
    const float* x;
    const float* W;
    if (in_sizes[0] == B_*C_*8) { x = (const float*)d_in[0]; W = (const float*)d_in[1]; }
    else                        { x = (const float*)d_in[1]; W = (const float*)d_in[0]; }
    float* out = (float*)d_out;

    k1_gemm<<<dim3(CCH_, 4), 320>>>(x, W);
    k_red_s0<<<B_, 160>>>();                       // s0 partials -> v1
    k2_pass<1><<<dim3(QCH_, B_), 256>>>();         // logit=u.v1 -> partial s (g_sp)
    k2_pass<2><<<dim3(QCH_, B_), 256>>>();         // logit=u.(v1+v2) -> g_sp2
    k_red_out<<<B_, 160>>>(out);                   // -> v3 = output
}

// round 12
// speedup vs baseline: 1.2275x; 1.1312x over previous
#include <cuda_runtime.h>
#include <cuda_fp16.h>

#define B_  256
#define C_  1152
#define N_  10
#define ND_ 160          // N_*D_
#define CCH_ 144         // k1 c-chunks of 8
#define QCH_ 4           // routing c-chunks of 288

// u_hat scratch (fp16), per (b,c) p-layout: [g(0..1)][n(0..9)][8]; d = g*8+dd
__device__ unsigned short g_uhat[(size_t)256*1152*160];
// per-c-chunk partial sums of u_hat over c (P-LAYOUT): [cchunk(144)][b][160]
__device__ float g_s0p[(size_t)CCH_*256*160];
// routing per-chunk partial s: [qchunk(4)][b][160] PLAIN layout (two buffers)
__device__ float g_sp [(size_t)QCH_*256*160];
__device__ float g_sp2[(size_t)QCH_*256*160];
// v1 per b, PLAIN layout
__device__ float g_v[(size_t)256*160];

// ---------------------------------------------------------------------------
// K1: u_hat[b,n,c,d] = sum_i W[n,c,d,i]*x[b,c,i]
// grid (144 c-chunks of 8, 4 b-chunks of 64), 320 threads:
// warp = n, lane>>3 = q (d-quarter), lane&7 = c_local. W in regs, x in smem.
// u_hat staged through smem in 8-b batches -> coalesced STG.128 sweeps.
// s0 partials computed FROM the staged smem tile (no shuffles).
// ---------------------------------------------------------------------------
__global__ __launch_bounds__(320, 3) void k1_gemm(const float* __restrict__ x,
                                                  const float* __restrict__ W)
{
    __shared__ float xs[64*64];                         // 16 KB
    __shared__ alignas(16) unsigned short usm[8*8*168]; // 21 KB: [bl][cl][168 pad]

    const int t    = threadIdx.x;
    const int n    = t >> 5;          // warp id = output capsule
    const int lane = t & 31;
    const int q    = lane >> 3;       // d-quarter 0..3
    const int cl   = lane & 7;        // c within block
    const int c    = blockIdx.x * 8 + cl;
    const int b0   = blockIdx.y * 64;

    // W regs: Wr[dd*8+i] = W[n][c][q*4+dd][i]
    float Wr[32];
    {
        const float4* Wp = reinterpret_cast<const float4*>(
            W + ((size_t)(n*C_ + c))*128 + q*32);
#pragma unroll
        for (int k = 0; k < 8; ++k) {
            float4 f = Wp[k];
            Wr[4*k]=f.x; Wr[4*k+1]=f.y; Wr[4*k+2]=f.z; Wr[4*k+3]=f.w;
        }
    }

    // cooperative x stage: 64 b's x 64 floats (8 c x 8 i), contiguous per b
    for (int idx = t; idx < 1024; idx += 320) {
        int bl = idx >> 4;            // 16 float4 per b
        int r  = idx & 15;
        reinterpret_cast<float4*>(xs)[bl*16 + r] =
            reinterpret_cast<const float4*>(
                x + (size_t)(b0 + bl)*(C_*8) + blockIdx.x*64)[r];
    }
    __syncthreads();

    // p-layout inner offset for this thread's 4 d's (d = q*4..q*4+3)
    const int poff = (q>>1)*80 + n*8 + (q&1)*4;

    for (int bg = 0; bg < 8; ++bg) {
        const int b_base = b0 + bg*8;

#pragma unroll
        for (int bl = 0; bl < 8; ++bl) {
            const float4* xr = reinterpret_cast<const float4*>(
                xs + (bg*8 + bl)*64 + cl*8);
            float4 f0 = xr[0], f1 = xr[1];
            float xv[8];
            xv[0]=f0.x; xv[1]=f0.y; xv[2]=f0.z; xv[3]=f0.w;
            xv[4]=f1.x; xv[5]=f1.y; xv[6]=f1.z; xv[7]=f1.w;

            float u[4];
#pragma unroll
            for (int dd = 0; dd < 4; ++dd) {
                float a = 0.f;
#pragma unroll
                for (int i = 0; i < 8; ++i) a = fmaf(Wr[dd*8+i], xv[i], a);
                u[dd] = a;
            }

            // pack fp16, stage into smem
            __half2 h01 = __floats2half2_rn(u[0], u[1]);
            __half2 h23 = __floats2half2_rn(u[2], u[3]);
            uint2 val;
            val.x = *reinterpret_cast<unsigned int*>(&h01);
            val.y = *reinterpret_cast<unsigned int*>(&h23);
            *reinterpret_cast<uint2*>(usm + (bl*8 + cl)*168 + poff) = val;
        }
        __syncthreads();

        // coalesced u_hat sweep: 8 b x 8 c x 160 halfs = 1280 uint4
#pragma unroll
        for (int it = 0; it < 4; ++it) {
            int j   = it*320 + t;          // 0..1279
            int bl2 = j / 160;
            int r   = j - bl2*160;
            int cL  = r / 20;
            int h   = r - cL*20;           // uint4 index within c (8 halfs each)
            uint4 v = *reinterpret_cast<const uint4*>(usm + (bl2*8 + cL)*168 + h*8);
            *reinterpret_cast<uint4*>(
                g_uhat + (size_t)(b_base + bl2)*(C_*160)
                       + (size_t)(blockIdx.x*8 + cL)*160 + h*8) = v;
        }

        // s0 partials from staged tile: sum over the 8 c's per (b, position)
        // 8 b x 80 half2-positions = 640 tasks, 2 per thread. p-layout output.
#pragma unroll
        for (int rr = 0; rr < 2; ++rr) {
            int task = rr*320 + t;         // 0..639
            int bl2  = task / 80;
            int pos2 = task - bl2*80;      // half2 position 0..79
            float ax = 0.f, ay = 0.f;
#pragma unroll
            for (int cc = 0; cc < 8; ++cc) {
                __half2 h = *reinterpret_cast<const __half2*>(
                    usm + (bl2*8 + cc)*168 + pos2*2);
                float2 f = __half22float2(h);
                ax += f.x; ay += f.y;
            }
            *reinterpret_cast<float2*>(
                g_s0p + ((size_t)blockIdx.x*B_ + (b_base + bl2))*ND_ + pos2*2) =
                make_float2(ax, ay);
        }
        __syncthreads();
    }
}

// ---------------------------------------------------------------------------
// K_red_s0: v1 = squash(0.1 * sum of 144 s0 partials). grid 256, 160 threads.
// Input p-layout, output PLAIN layout.
// ---------------------------------------------------------------------------
__global__ __launch_bounds__(160) void k_red_s0()
{
    __shared__ float sm[ND_];
    const int b = blockIdx.x;
    const int t = threadIdx.x;

    float s = 0.f;
#pragma unroll 4
    for (int k = 0; k < CCH_; ++k)
        s += g_s0p[((size_t)k*B_ + b)*ND_ + t];
    s *= 0.1f;
    sm[t] = s;
    __syncthreads();

    const int g2 = t / 80, rem = t - g2*80, nn = rem >> 3, dd = rem & 7;
    float sq = 0.f;
#pragma unroll
    for (int gg = 0; gg < 2; ++gg)
#pragma unroll
        for (int d2 = 0; d2 < 8; ++d2) {
            float v = sm[gg*80 + nn*8 + d2]; sq += v*v;
        }
    float f = sq / (1.f + sq) / (sqrtf(sq) + 1e-8f);
    g_v[(size_t)b*ND_ + nn*16 + g2*8 + dd] = s * f;   // plain layout
}

// ---------------------------------------------------------------------------
// K_red_out: v = squash(sum of 4 pass-2 partials) -> out. grid 256, 160 thr.
// g_sp2 is plain layout; shfl over the 16 consecutive d's works.
// ---------------------------------------------------------------------------
__global__ __launch_bounds__(160) void k_red_out(float* __restrict__ out)
{
    const int b = blockIdx.x;
    const int t = threadIdx.x;

    float s = 0.f;
#pragma unroll
    for (int k = 0; k < QCH_; ++k)
        s += g_sp2[((size_t)k*B_ + b)*ND_ + t];

    float sq = s*s;
#pragma unroll
    for (int o = 1; o < 16; o <<= 1)
        sq += __shfl_xor_sync(0xffffffffu, sq, o);
    float f = sq / (1.f + sq) / (sqrtf(sq) + 1e-8f);
    out[(size_t)b*ND_ + t] = s * f;
}

// ---------------------------------------------------------------------------
// K2 pass: one routing iteration over a 288-c chunk. No logit storage:
//   PASS 1: vcur = v1.   PASS 2: vcur = v1 + v2 (computed in prologue).
//   logit = u . vcur in both passes.
// grid (4 qchunks, 256 b), 256 threads = 8 warps.
// lane = g*16+n: g = c-parity, n = capsule. Two independent chains per iter.
// ---------------------------------------------------------------------------
__device__ __forceinline__ void cvt8(const uint4& H, float* u)
{
    unsigned int r[4] = {H.x, H.y, H.z, H.w};
#pragma unroll
    for (int k = 0; k < 4; ++k) {
        __half2 h = *reinterpret_cast<__half2*>(&r[k]);
        float2 f = __half22float2(h);
        u[2*k] = f.x; u[2*k+1] = f.y;
    }
}

__device__ __forceinline__ void route_step(
    uint4 X0, uint4 X1, bool act,
    const float* __restrict__ vreg, float* __restrict__ sacc)
{
    float u[16];
    cvt8(X0, u);
    cvt8(X1, u + 8);

    float uv0 = 0.f, uv1 = 0.f;
#pragma unroll
    for (int d = 0; d < 16; d += 2) {
        uv0 = fmaf(u[d],   vreg[d],   uv0);
        uv1 = fmaf(u[d+1], vreg[d+1], uv1);
    }
    float logit = uv0 + uv1;

    float e = act ? __expf(logit) : 0.f;
    float ssum = e;
#pragma unroll
    for (int o = 8; o; o >>= 1)
        ssum += __shfl_xor_sync(0xffffffffu, ssum, o);
    float coef = e * __fdividef(1.f, ssum);

#pragma unroll
    for (int d = 0; d < 16; ++d) sacc[d] = fmaf(coef, u[d], sacc[d]);
}

template<int PASS>
__global__ __launch_bounds__(256, 3) void k2_pass()
{
    __shared__ float sred[8*ND_];
    __shared__ float vsm[ND_];

    const int  qc = blockIdx.x;       // c-chunk 0..3 (288 c each)
    const int  b  = blockIdx.y;
    const int  t  = threadIdx.x;
    const int  w  = t >> 5;
    const int  l  = t & 31;
    const int  g  = l >> 4;
    const int  n  = l & 15;
    const bool act = (n < N_);

    // prologue: vcur into vsm (plain layout)
    if (t < ND_) {
        if (PASS == 1) {
            vsm[t] = g_v[(size_t)b*ND_ + t];
        } else {
            float s = 0.f;
#pragma unroll
            for (int k = 0; k < QCH_; ++k)
                s += g_sp[((size_t)k*B_ + b)*ND_ + t];
            float sq = s*s;
#pragma unroll
            for (int o = 1; o < 16; o <<= 1)
                sq += __shfl_xor_sync(0xffffffffu, sq, o);
            float f = sq / (1.f + sq) / (sqrtf(sq) + 1e-8f);
            vsm[t] = s * f + g_v[(size_t)b*ND_ + t];    // v1 + v2
        }
    }
    __syncthreads();

    float vreg[16];
#pragma unroll
    for (int d = 0; d < 16; ++d) vreg[d] = act ? vsm[n*16 + d] : 0.f;

    float sacc[16];
#pragma unroll
    for (int d = 0; d < 16; ++d) sacc[d] = 0.f;

    const unsigned short* uh = g_uhat + (size_t)b*(C_*160);
    int c = qc*288 + 2*w + g;

    uint4 A0, A1, B0, B1;
    if (act) {
        const unsigned short* p = uh + (size_t)c*160 + n*8;
        A0 = *reinterpret_cast<const uint4*>(p);
        A1 = *reinterpret_cast<const uint4*>(p + 80);
        const unsigned short* pb = p + 16*160;
        B0 = *reinterpret_cast<const uint4*>(pb);
        B1 = *reinterpret_cast<const uint4*>(pb + 80);
    }

    for (int i = 0; i < 18; i += 2) {
        uint4 a0 = A0, a1 = A1;
        if (i + 2 < 18 && act) {
            const unsigned short* p = uh + (size_t)(c+32)*160 + n*8;
            A0 = *reinterpret_cast<const uint4*>(p);
            A1 = *reinterpret_cast<const uint4*>(p + 80);
        }
        route_step(a0, a1, act, vreg, sacc);

        uint4 b0 = B0, b1 = B1;
        if (i + 3 < 18 && act) {
            const unsigned short* p = uh + (size_t)(c+48)*160 + n*8;
            B0 = *reinterpret_cast<const uint4*>(p);
            B1 = *reinterpret_cast<const uint4*>(p + 80);
        }
        route_step(b0, b1, act, vreg, sacc);

        c += 32;
    }

    // combine the two c-parity halves of each warp
#pragma unroll
    for (int d = 0; d < 16; ++d)
        sacc[d] += __shfl_xor_sync(0xffffffffu, sacc[d], 16);

    if (g == 0 && act) {
#pragma unroll
        for (int d = 0; d < 16; ++d) sred[w*ND_ + n*16 + d] = sacc[d];
    }
    __syncthreads();
    if (t < ND_) {
        float a = 0.f;
#pragma unroll
        for (int k = 0; k < 8; ++k) a += sred[k*ND_ + t];
        float* dst = (PASS == 1) ? g_sp : g_sp2;
        dst[((size_t)qc*B_ + b)*ND_ + t] = a;
    }
}

// ---------------------------------------------------------------------------
extern "C" void kernel_launch(void* const* d_in, const int* in_sizes, int n_in,
                              void* d_out, int out_size)
{
    const float* x;
    const float* W;
    if (in_sizes[0] == B_*C_*8) { x = (const float*)d_in[0]; W = (const float*)d_in[1]; }
    else                        { x = (const float*)d_in[1]; W = (const float*)d_in[0]; }
    float* out = (float*)d_out;

    k1_gemm<<<dim3(CCH_, 4), 320>>>(x, W);
    k_red_s0<<<B_, 160>>>();                       // s0 partials -> v1
    k2_pass<1><<<dim3(QCH_, B_), 256>>>();         // logit=u.v1 -> partial s (g_sp)
    k2_pass<2><<<dim3(QCH_, B_), 256>>>();         // logit=u.(v1+v2) -> g_sp2
    k_red_out<<<B_, 160>>>(out);                   // -> v3 = output
}

// round 14
// speedup vs baseline: 1.4019x; 1.1421x over previous
#include <cuda_runtime.h>
#include <cuda_fp16.h>

#define B_  256
#define C_  1152
#define N_  10
#define ND_ 160          // N_*D_
#define CCH_ 144         // k1 c-chunks of 8
#define QCH_ 4           // routing c-chunks of 288

// u_hat scratch (fp16), per (b,c) p-layout: [g(0..1)][n(0..9)][8]; d = g*8+dd
__device__ unsigned short g_uhat[(size_t)256*1152*160];
// per-c-chunk partial sums of u_hat over c (P-LAYOUT): [cchunk(144)][b][160]
__device__ float g_s0p[(size_t)CCH_*256*160];
// routing per-chunk partial s: [qchunk(4)][b][160] PLAIN layout (two buffers)
__device__ float g_sp [(size_t)QCH_*256*160];
__device__ float g_sp2[(size_t)QCH_*256*160];
// v1 per b, PLAIN layout
__device__ float g_v[(size_t)256*160];

// ---------------------------------------------------------------------------
// K1: u_hat[b,n,c,d] = sum_i W[n,c,d,i]*x[b,c,i]   (unchanged from R12)
// ---------------------------------------------------------------------------
__global__ __launch_bounds__(320, 3) void k1_gemm(const float* __restrict__ x,
                                                  const float* __restrict__ W)
{
    __shared__ float xs[64*64];                         // 16 KB
    __shared__ alignas(16) unsigned short usm[8*8*168]; // 21 KB: [bl][cl][168 pad]

    const int t    = threadIdx.x;
    const int n    = t >> 5;          // warp id = output capsule
    const int lane = t & 31;
    const int q    = lane >> 3;       // d-quarter 0..3
    const int cl   = lane & 7;        // c within block
    const int c    = blockIdx.x * 8 + cl;
    const int b0   = blockIdx.y * 64;

    float Wr[32];
    {
        const float4* Wp = reinterpret_cast<const float4*>(
            W + ((size_t)(n*C_ + c))*128 + q*32);
#pragma unroll
        for (int k = 0; k < 8; ++k) {
            float4 f = Wp[k];
            Wr[4*k]=f.x; Wr[4*k+1]=f.y; Wr[4*k+2]=f.z; Wr[4*k+3]=f.w;
        }
    }

    for (int idx = t; idx < 1024; idx += 320) {
        int bl = idx >> 4;
        int r  = idx & 15;
        reinterpret_cast<float4*>(xs)[bl*16 + r] =
            reinterpret_cast<const float4*>(
                x + (size_t)(b0 + bl)*(C_*8) + blockIdx.x*64)[r];
    }
    __syncthreads();

    const int poff = (q>>1)*80 + n*8 + (q&1)*4;

    for (int bg = 0; bg < 8; ++bg) {
        const int b_base = b0 + bg*8;

#pragma unroll
        for (int bl = 0; bl < 8; ++bl) {
            const float4* xr = reinterpret_cast<const float4*>(
                xs + (bg*8 + bl)*64 + cl*8);
            float4 f0 = xr[0], f1 = xr[1];
            float xv[8];
            xv[0]=f0.x; xv[1]=f0.y; xv[2]=f0.z; xv[3]=f0.w;
            xv[4]=f1.x; xv[5]=f1.y; xv[6]=f1.z; xv[7]=f1.w;

            float u[4];
#pragma unroll
            for (int dd = 0; dd < 4; ++dd) {
                float a = 0.f;
#pragma unroll
                for (int i = 0; i < 8; ++i) a = fmaf(Wr[dd*8+i], xv[i], a);
                u[dd] = a;
            }

            __half2 h01 = __floats2half2_rn(u[0], u[1]);
            __half2 h23 = __floats2half2_rn(u[2], u[3]);
            uint2 val;
            val.x = *reinterpret_cast<unsigned int*>(&h01);
            val.y = *reinterpret_cast<unsigned int*>(&h23);
            *reinterpret_cast<uint2*>(usm + (bl*8 + cl)*168 + poff) = val;
        }
        __syncthreads();

#pragma unroll
        for (int it = 0; it < 4; ++it) {
            int j   = it*320 + t;
            int bl2 = j / 160;
            int r   = j - bl2*160;
            int cL  = r / 20;
            int h   = r - cL*20;
            uint4 v = *reinterpret_cast<const uint4*>(usm + (bl2*8 + cL)*168 + h*8);
            *reinterpret_cast<uint4*>(
                g_uhat + (size_t)(b_base + bl2)*(C_*160)
                       + (size_t)(blockIdx.x*8 + cL)*160 + h*8) = v;
        }

#pragma unroll
        for (int rr = 0; rr < 2; ++rr) {
            int task = rr*320 + t;
            int bl2  = task / 80;
            int pos2 = task - bl2*80;
            float ax = 0.f, ay = 0.f;
#pragma unroll
            for (int cc = 0; cc < 8; ++cc) {
                __half2 h = *reinterpret_cast<const __half2*>(
                    usm + (bl2*8 + cc)*168 + pos2*2);
                float2 f = __half22float2(h);
                ax += f.x; ay += f.y;
            }
            *reinterpret_cast<float2*>(
                g_s0p + ((size_t)blockIdx.x*B_ + (b_base + bl2))*ND_ + pos2*2) =
                make_float2(ax, ay);
        }
        __syncthreads();
    }
}

// ---------------------------------------------------------------------------
// K_red_s0: v1 = squash(0.1 * sum of 144 s0 partials). grid 256, 640 threads
// (4 groups x 36 chunks -> smem combine). Input p-layout, output PLAIN.
// ---------------------------------------------------------------------------
__global__ __launch_bounds__(640) void k_red_s0()
{
    __shared__ float part[4*ND_];
    __shared__ float sm[ND_];
    const int b = blockIdx.x;
    const int t = threadIdx.x;

    {
        const int grp = t / ND_, pos = t - grp*ND_;
        float a0=0.f, a1=0.f, a2=0.f, a3=0.f;
        const float* sp = g_s0p + (size_t)b*ND_ + pos;
#pragma unroll 4
        for (int k = grp*36; k < grp*36 + 36; k += 4) {
            a0 += sp[(size_t)(k+0)*(B_*ND_)];
            a1 += sp[(size_t)(k+1)*(B_*ND_)];
            a2 += sp[(size_t)(k+2)*(B_*ND_)];
            a3 += sp[(size_t)(k+3)*(B_*ND_)];
        }
        part[grp*ND_ + pos] = a0+a1+a2+a3;
    }
    __syncthreads();
    if (t < ND_) {
        sm[t] = (part[t] + part[ND_+t] + part[2*ND_+t] + part[3*ND_+t]) * 0.1f;
    }
    __syncthreads();
    if (t < ND_) {
        const int g2 = t / 80, rem = t - g2*80, nn = rem >> 3, dd = rem & 7;
        float s = sm[t];
        float sq = 0.f;
#pragma unroll
        for (int gg = 0; gg < 2; ++gg)
#pragma unroll
            for (int d2 = 0; d2 < 8; ++d2) {
                float v = sm[gg*80 + nn*8 + d2]; sq += v*v;
            }
        float f = sq / (1.f + sq) / (sqrtf(sq) + 1e-8f);
        g_v[(size_t)b*ND_ + nn*16 + g2*8 + dd] = s * f;   // plain layout
    }
}

// ---------------------------------------------------------------------------
// K_red_out: v = squash(sum of 4 pass-2 partials) -> out. grid 256, 160 thr.
// ---------------------------------------------------------------------------
__global__ __launch_bounds__(160) void k_red_out(float* __restrict__ out)
{
    const int b = blockIdx.x;
    const int t = threadIdx.x;

    float s = 0.f;
#pragma unroll
    for (int k = 0; k < QCH_; ++k)
        s += g_sp2[((size_t)k*B_ + b)*ND_ + t];

    float sq = s*s;
#pragma unroll
    for (int o = 1; o < 16; o <<= 1)
        sq += __shfl_xor_sync(0xffffffffu, sq, o);
    float f = sq / (1.f + sq) / (sqrtf(sq) + 1e-8f);
    out[(size_t)b*ND_ + t] = s * f;
}

// ---------------------------------------------------------------------------
// K2 pass: one routing iteration over a 288-c chunk.
//   PASS 1: vcur = v1.   PASS 2: vcur = v1 + v2 (prologue). logit = u.vcur.
// grid (4 qchunks, 256 b), 256 threads = 8 warps, 4 CTAs/SM.
// lane = g*16+n: g = D-HALF (8 d's each), n = capsule.
// Lanes (0,n),(1,n) cooperate on one c (1 uint4 each, shfl16 dot-combine);
// two chains (c = 2w, 2w+1) per iteration; 18 iterations.
// ---------------------------------------------------------------------------
__device__ __forceinline__ void route_step(
    uint4 X, bool act,
    const __half2* __restrict__ vh2, float* __restrict__ sacc)
{
    unsigned int r[4] = {X.x, X.y, X.z, X.w};
    const __half2* u2 = reinterpret_cast<const __half2*>(r);

    // half2 dot over this lane's 8 d's
    __half2 acc = __hmul2(u2[0], vh2[0]);
    acc = __hfma2(u2[1], vh2[1], acc);
    acc = __hfma2(u2[2], vh2[2], acc);
    acc = __hfma2(u2[3], vh2[3], acc);
    float2 fa = __half22float2(acc);
    float part = fa.x + fa.y;
    float logit = part + __shfl_xor_sync(0xffffffffu, part, 16);  // combine d-halves

    float e = act ? __expf(logit) : 0.f;
    float ssum = e;
#pragma unroll
    for (int o = 8; o; o >>= 1)
        ssum += __shfl_xor_sync(0xffffffffu, ssum, o);
    float coef = e * __fdividef(1.f, ssum);

    // accumulate this lane's 8 d's
#pragma unroll
    for (int k = 0; k < 4; ++k) {
        float2 f = __half22float2(u2[k]);
        sacc[2*k]   = fmaf(coef, f.x, sacc[2*k]);
        sacc[2*k+1] = fmaf(coef, f.y, sacc[2*k+1]);
    }
}

template<int PASS>
__global__ __launch_bounds__(256, 4) void k2_pass()
{
    __shared__ float sred[8*ND_];
    __shared__ float vsm[ND_];

    const int  qc = blockIdx.x;       // c-chunk 0..3 (288 c each)
    const int  b  = blockIdx.y;
    const int  t  = threadIdx.x;
    const int  w  = t >> 5;
    const int  l  = t & 31;
    const int  g  = l >> 4;           // d-half
    const int  n  = l & 15;
    const bool act = (n < N_);

    // prologue: vcur into vsm (plain layout)
    if (t < ND_) {
        if (PASS == 1) {
            vsm[t] = g_v[(size_t)b*ND_ + t];
        } else {
            float s = 0.f;
#pragma unroll
            for (int k = 0; k < QCH_; ++k)
                s += g_sp[((size_t)k*B_ + b)*ND_ + t];
            float sq = s*s;
#pragma unroll
            for (int o = 1; o < 16; o <<= 1)
                sq += __shfl_xor_sync(0xffffffffu, sq, o);
            float f = sq / (1.f + sq) / (sqrtf(sq) + 1e-8f);
            vsm[t] = s * f + g_v[(size_t)b*ND_ + t];    // v1 + v2
        }
    }
    __syncthreads();

    // this lane's v-slice as half2 (d = g*8 .. g*8+7)
    __half2 vh2[4];
#pragma unroll
    for (int k = 0; k < 4; ++k) {
        float vx = act ? vsm[n*16 + g*8 + 2*k]     : 0.f;
        float vy = act ? vsm[n*16 + g*8 + 2*k + 1] : 0.f;
        vh2[k] = __floats2half2_rn(vx, vy);
    }

    float sacc[8];
#pragma unroll
    for (int d = 0; d < 8; ++d) sacc[d] = 0.f;

    // lane's pointer: c-base qc*288 + 2w (+1 for chain B), slice g*80+n*8
    const unsigned short* uhA =
        g_uhat + (size_t)b*(C_*160) + (size_t)(qc*288 + 2*w)*160 + g*80 + n*8;
    const unsigned short* uhB = uhA + 160;

    uint4 A, Bv;
    if (act) {
        A  = *reinterpret_cast<const uint4*>(uhA);
        Bv = *reinterpret_cast<const uint4*>(uhB);
    }

    for (int i = 0; i < 18; ++i) {
        uint4 a = A;
        if (i < 17 && act)
            A = *reinterpret_cast<const uint4*>(uhA + (size_t)(i+1)*16*160);
        route_step(a, act, vh2, sacc);

        uint4 bb = Bv;
        if (i < 17 && act)
            Bv = *reinterpret_cast<const uint4*>(uhB + (size_t)(i+1)*16*160);
        route_step(bb, act, vh2, sacc);
    }

    // each lane owns plain d = g*8 + dd: no cross-lane combine needed
    if (act) {
#pragma unroll
        for (int d = 0; d < 8; ++d) sred[w*ND_ + n*16 + g*8 + d] = sacc[d];
    }
    __syncthreads();
    if (t < ND_) {
        float a = 0.f;
#pragma unroll
        for (int k = 0; k < 8; ++k) a += sred[k*ND_ + t];
        float* dst = (PASS == 1) ? g_sp : g_sp2;
        dst[((size_t)qc*B_ + b)*ND_ + t] = a;
    }
}

// ---------------------------------------------------------------------------
extern "C" void kernel_launch(void* const* d_in, const int* in_sizes, int n_in,
                              void* d_out, int out_size)
{
    const float* x;
    const float* W;
    if (in_sizes[0] == B_*C_*8) { x = (const float*)d_in[0]; W = (const float*)d_in[1]; }
    else                        { x = (const float*)d_in[1]; W = (const float*)d_in[0]; }
    float* out = (float*)d_out;

    k1_gemm<<<dim3(CCH_, 4), 320>>>(x, W);
    k_red_s0<<<B_, 640>>>();                       // s0 partials -> v1
    k2_pass<1><<<dim3(QCH_, B_), 256>>>();         // logit=u.v1 -> partial s (g_sp)
    k2_pass<2><<<dim3(QCH_, B_), 256>>>();         // logit=u.(v1+v2) -> g_sp2
    k_red_out<<<B_, 160>>>(out);                   // -> v3 = output
}